// round 4
// baseline (speedup 1.0000x reference)
#include <cuda_runtime.h>
#include <cuda_fp16.h>
#include <cstddef>

// Problem constants (fixed by the reference)
#define B_    4096
#define NIN_  512
#define L_    16
#define N_    512
#define K_    32
#define NOUT_ 256
#define TOTAL_ (NIN_ + L_ * N_)   // 8704
#define BG_   (B_ / 8)            // 512 groups of 8 halves (16B) across batch

#define NBLOCKS_ 512

// Activation buffer, transposed + fp16: g_buf[feature * B + batch] (~71 MB)
__device__ __half g_buf[(size_t)TOTAL_ * B_];

// Grid barrier state
__device__ unsigned g_bar_count = 0;
__device__ unsigned g_bar_gen   = 0;

__device__ __forceinline__ void grid_sync_() {
    __syncthreads();
    if (threadIdx.x == 0 && threadIdx.y == 0) {
        __threadfence();
        unsigned gen = *(volatile unsigned*)&g_bar_gen;
        if (atomicAdd(&g_bar_count, 1u) == NBLOCKS_ - 1u) {
            g_bar_count = 0;
            __threadfence();
            atomicAdd(&g_bar_gen, 1u);
        } else {
            while (*(volatile unsigned*)&g_bar_gen == gen) { __nanosleep(64); }
        }
        __threadfence();
    }
    __syncthreads();
}

__device__ __forceinline__ float sigmoidf_(float v) {
    return 1.0f / (1.0f + __expf(-v));
}

// 4 packed f32x2 accumulators <- w * (8 halves)
__device__ __forceinline__ void fma8p_(unsigned long long* acc,
                                       unsigned long long wpack, uint4 v) {
    const unsigned* vw = &v.x;
#pragma unroll
    for (int i = 0; i < 4; ++i) {
        __half2 h = *reinterpret_cast<const __half2*>(&vw[i]);
        float2 f = __half22float2(h);
        unsigned long long p;
        asm("mov.b64 %0, {%1, %2};" : "=l"(p) : "f"(f.x), "f"(f.y));
        asm("fma.rn.f32x2 %0, %1, %2, %0;" : "+l"(acc[i]) : "l"(p), "l"(wpack));
    }
}

__device__ __forceinline__ float2 unpack2_(unsigned long long p) {
    float2 r;
    asm("mov.b64 {%0, %1}, %2;" : "=f"(r.x), "=f"(r.y) : "l"(p));
    return r;
}

// ---------------------------------------------------------------------------
// One persistent kernel: transpose -> 16 sparse layers -> output layer.
// 512 blocks of (32,8); all blocks co-resident (4/SM max via launch bounds).
// ---------------------------------------------------------------------------
__global__ void __launch_bounds__(256, 4) fused_net_kernel(
    const float* __restrict__ x,       // (B, NIN)
    const float* __restrict__ W,       // (L, N, K)
    const float* __restrict__ bias,    // (L, N)
    const float* __restrict__ W_out,   // (NOUT, K)
    const float* __restrict__ b_out,   // (NOUT,)
    const int*   __restrict__ idx,     // (L, N, K)
    const int*   __restrict__ idx_out, // (NOUT, K)
    float* __restrict__ out)           // (B, NOUT)
{
    __shared__ float s_tr[32][33];     // transpose tile
    __shared__ int2  s_iw[8][K_];      // (idx, weight-bits) per neuron
    __shared__ float s_tile[8][256];   // output transpose tile

    const int tx = threadIdx.x, ty = threadIdx.y;
    const int pb = blockIdx.x;

    // ---------------- Phase 0: transpose x -> g_buf (fp16, feature-major) ----
    // 2048 tiles of 32x32; each block does 4 tiles.
    for (int i = 0; i < 4; ++i) {
        const int t  = pb * 4 + i;
        const int f0 = (t % 16) * 32;
        const int b0 = (t / 16) * 32;
#pragma unroll
        for (int r = 0; r < 4; ++r) {
            const int y = ty + 8 * r;
            s_tr[y][tx] = x[(size_t)(b0 + y) * NIN_ + (f0 + tx)];
        }
        __syncthreads();
#pragma unroll
        for (int r = 0; r < 4; ++r) {
            const int y = ty + 8 * r;
            g_buf[(size_t)(f0 + y) * B_ + (b0 + tx)] = __float2half(s_tr[tx][y]);
        }
        __syncthreads();
    }
    grid_sync_();

    // ---------------- Phases 1..16: sparse layers ----------------------------
    const uint4* __restrict__ buf16 = reinterpret_cast<const uint4*>(g_buf);
    const int bx = pb & 7;          // 8 q-chunks
    const int by = pb >> 3;         // 64 neuron-chunks
    const int q  = bx * 32 + tx;    // handles groups q and q+256
    const int n  = by * 8 + ty;

    for (int l = 0; l < L_; ++l) {
        const int*   l_idx = idx  + (size_t)l * N_ * K_;
        const float* l_W   = W    + (size_t)l * N_ * K_;
        {
            int2 p;
            p.x = l_idx[n * K_ + tx];
            p.y = __float_as_int(l_W[n * K_ + tx]);
            s_iw[ty][tx] = p;
        }
        __syncthreads();

        unsigned long long acc[8];
#pragma unroll
        for (int i = 0; i < 8; ++i) acc[i] = 0ull;

#pragma unroll
        for (int k = 0; k < K_; ++k) {
            const int2  iw = s_iw[ty][k];
            const float w  = __int_as_float(iw.y);
            unsigned long long wpack;
            asm("mov.b64 %0, {%1, %1};" : "=l"(wpack) : "f"(w));
            const size_t base = (size_t)iw.x * BG_ + q;
            uint4 v0 = buf16[base];
            uint4 v1 = buf16[base + 256];
            fma8p_(acc,     wpack, v0);
            fma8p_(acc + 4, wpack, v1);
        }

        const float bb = bias[(size_t)l * N_ + n];
        uint4 o0, o1;
        {
            unsigned* ow = &o0.x;
#pragma unroll
            for (int i = 0; i < 4; ++i) {
                float2 f = unpack2_(acc[i]);
                __half2 r = __floats2half2_rn(sigmoidf_(f.x + bb), sigmoidf_(f.y + bb));
                ow[i] = *reinterpret_cast<unsigned*>(&r);
            }
        }
        {
            unsigned* ow = &o1.x;
#pragma unroll
            for (int i = 0; i < 4; ++i) {
                float2 f = unpack2_(acc[4 + i]);
                __half2 r = __floats2half2_rn(sigmoidf_(f.x + bb), sigmoidf_(f.y + bb));
                ow[i] = *reinterpret_cast<unsigned*>(&r);
            }
        }
        const size_t obase = (size_t)(NIN_ + l * N_ + n) * BG_ + q;
        reinterpret_cast<uint4*>(g_buf)[obase]       = o0;
        reinterpret_cast<uint4*>(g_buf)[obase + 256] = o1;

        grid_sync_();   // also covers the smem reuse of s_iw across layers
    }

    // ---------------- Phase 17: output layer ---------------------------------
    // 512 blocks: bx2 in [0,16) over q, by2 in [0,32) over neuron octets
    {
        const int bx2 = pb & 15;
        const int by2 = pb >> 4;
        const int o0n = by2 * 8;
        const int o   = o0n + ty;
        const int q2  = bx2 * 32 + tx;

        {
            int2 p;
            p.x = idx_out[o * K_ + tx];
            p.y = __float_as_int(W_out[o * K_ + tx]);
            s_iw[ty][tx] = p;
        }
        __syncthreads();

        unsigned long long acc[4];
#pragma unroll
        for (int i = 0; i < 4; ++i) acc[i] = 0ull;

#pragma unroll
        for (int k = 0; k < K_; ++k) {
            const int2  iw = s_iw[ty][k];
            const float w  = __int_as_float(iw.y);
            unsigned long long wpack;
            asm("mov.b64 %0, {%1, %1};" : "=l"(wpack) : "f"(w));
            uint4 v = buf16[(size_t)iw.x * BG_ + q2];
            fma8p_(acc, wpack, v);
        }

        const float bb = b_out[o];
        const int bl = tx * 8;
#pragma unroll
        for (int i = 0; i < 4; ++i) {
            float2 f = unpack2_(acc[i]);
            s_tile[ty][bl + 2 * i]     = sigmoidf_(f.x + bb);
            s_tile[ty][bl + 2 * i + 1] = sigmoidf_(f.y + bb);
        }
        __syncthreads();

        const int t = ty * 32 + tx;
        const int b = bx2 * 256 + t;
        float4 w0, w1;
        w0.x = s_tile[0][t]; w0.y = s_tile[1][t]; w0.z = s_tile[2][t]; w0.w = s_tile[3][t];
        w1.x = s_tile[4][t]; w1.y = s_tile[5][t]; w1.z = s_tile[6][t]; w1.w = s_tile[7][t];
        float4* dst = reinterpret_cast<float4*>(out + (size_t)b * NOUT_ + o0n);
        dst[0] = w0;
        dst[1] = w1;
    }
}

// ---------------------------------------------------------------------------
// kernel_launch: inputs in metadata order:
//   0: x (B,NIN) f32   1: W (L,N,K) f32   2: b (L,N) f32
//   3: W_out (NOUT,K) f32   4: b_out (NOUT,) f32
//   5: idx (L,N,K) i32      6: idx_out (NOUT,K) i32
// ---------------------------------------------------------------------------
extern "C" void kernel_launch(void* const* d_in, const int* in_sizes, int n_in,
                              void* d_out, int out_size) {
    const float* x     = (const float*)d_in[0];
    const float* W     = (const float*)d_in[1];
    const float* b     = (const float*)d_in[2];
    const float* W_out = (const float*)d_in[3];
    const float* b_out = (const float*)d_in[4];
    const int*   idx     = (const int*)d_in[5];
    const int*   idx_out = (const int*)d_in[6];
    float* out = (float*)d_out;

    dim3 blk(32, 8);
    fused_net_kernel<<<NBLOCKS_, blk>>>(x, W, b, W_out, b_out, idx, idx_out, out);
}